// round 2
// baseline (speedup 1.0000x reference)
#include <cuda_runtime.h>
#include <stdint.h>

// NeighborNoiser: out = (up*ur + down*dr + left*lr + right*rr) / (ur+dr+lr+rr)
// Weights reproduce jax.random.uniform(key(42), (4,8,3,1024,1024)) under the
// PARTITIONABLE threefry path (JAX >= 0.5 default):
//   bits[i] = fold( threefry2x32(key=(0,42), x0 = i>>32 (=0), x1 = i) )
//   fold(b1, b2) = b1 ^ b2   for 32-bit draws
//   u = bitcast_f32((bits>>9) | 0x3f800000) - 1.0

#define N1 25165824u                    // 8*3*1024*1024 (one weight plane-set)

__device__ __forceinline__ void tf_round(uint32_t& x0, uint32_t& x1, int d) {
    x0 += x1;
    x1 = __funnelshift_l(x1, x1, d);    // rotl32, single SHF
    x1 ^= x0;
}

// threefry2x32 with key (0, 42), counter (0, ctr); returns out0 ^ out1.
__device__ __forceinline__ uint32_t tf_bits(uint32_t ctr) {
    const uint32_t ks0 = 0u;
    const uint32_t ks1 = 42u;
    const uint32_t ks2 = 0x1BD11BDAu ^ ks0 ^ ks1;   // 0x1BD11BF0

    uint32_t x0 = 0u + ks0;             // hi counter is 0 (n < 2^32)
    uint32_t x1 = ctr + ks1;

    tf_round(x0, x1, 13); tf_round(x0, x1, 15); tf_round(x0, x1, 26); tf_round(x0, x1, 6);
    x0 += ks1; x1 += ks2 + 1u;
    tf_round(x0, x1, 17); tf_round(x0, x1, 29); tf_round(x0, x1, 16); tf_round(x0, x1, 24);
    x0 += ks2; x1 += ks0 + 2u;
    tf_round(x0, x1, 13); tf_round(x0, x1, 15); tf_round(x0, x1, 26); tf_round(x0, x1, 6);
    x0 += ks0; x1 += ks1 + 3u;
    tf_round(x0, x1, 17); tf_round(x0, x1, 29); tf_round(x0, x1, 16); tf_round(x0, x1, 24);
    x0 += ks1; x1 += ks2 + 4u;
    tf_round(x0, x1, 13); tf_round(x0, x1, 15); tf_round(x0, x1, 26); tf_round(x0, x1, 6);
    x0 += ks2; x1 += ks0 + 5u;

    return x0 ^ x1;
}

__device__ __forceinline__ float u01(uint32_t bits) {
    return __uint_as_float((bits >> 9) | 0x3f800000u) - 1.0f;
}

__global__ __launch_bounds__(256)
void neighbor_noiser_kernel(const float* __restrict__ t, float* __restrict__ out) {
    uint32_t j = blockIdx.x * blockDim.x + threadIdx.x;   // linear idx in (24,1024,1024)

    uint32_t plane = j >> 20;
    uint32_t pos   = j & 0xFFFFFu;
    uint32_t y     = pos >> 10;
    uint32_t x     = pos & 1023u;

    const float* p = t + ((size_t)plane << 20);
    uint32_t yu = (y == 0u)    ? 0u     : y - 1u;
    uint32_t yd = (y == 1023u) ? 1023u  : y + 1u;
    uint32_t xl = (x == 0u)    ? 0u     : x - 1u;
    uint32_t xr = (x == 1023u) ? 1023u  : x + 1u;

    float up = __ldg(p + (yu << 10) + x);
    float dn = __ldg(p + (yd << 10) + x);
    float lf = __ldg(p + (y  << 10) + xl);
    float rt = __ldg(p + (y  << 10) + xr);

    // 4 independent hash chains (ILP covers the 4-cyc ALU dep latency)
    uint32_t bu = tf_bits(j);
    uint32_t bd = tf_bits(j + N1);
    uint32_t bl = tf_bits(j + 2u * N1);
    uint32_t br = tf_bits(j + 3u * N1);

    float ur = u01(bu);
    float dr = u01(bd);
    float lr = u01(bl);
    float rr = u01(br);

    float s   = (ur + dr) + (lr + rr);
    float num = fmaf(up, ur, fmaf(dn, dr, fmaf(lf, lr, rt * rr)));
    out[j] = __fdividef(num, s);
}

extern "C" void kernel_launch(void* const* d_in, const int* in_sizes, int n_in,
                              void* d_out, int out_size) {
    const float* t = (const float*)d_in[0];
    float* out = (float*)d_out;
    (void)in_sizes; (void)n_in; (void)out_size;

    const uint32_t threads = 256;
    const uint32_t blocks = N1 / threads;    // 98304, exact
    neighbor_noiser_kernel<<<blocks, threads>>>(t, out);
}